// round 15
// baseline (speedup 1.0000x reference)
#include <cuda_runtime.h>

#define VOCAB 10000
#define EMB   16
#define HID   32
#define NCLS  2
#define BATCH 4096
#define SEQ   512

typedef unsigned long long ull;

// Projected embedding table: proj[t][h] = sum_e emb[t][e]*W_ih[h][e] + b_ih[h] + b_hh[h]
__device__ float g_proj[VOCAB * HID];

__global__ void build_proj_kernel(const float* __restrict__ emb,
                                  const float* __restrict__ W_ih,
                                  const float* __restrict__ b_ih,
                                  const float* __restrict__ b_hh) {
    int t    = blockIdx.x * (blockDim.x >> 5) + (threadIdx.x >> 5);
    int lane = threadIdx.x & 31;
    if (t >= VOCAB) return;
    float acc = __ldg(b_ih + lane) + __ldg(b_hh + lane);
#pragma unroll
    for (int e = 0; e < EMB; e++) {
        acc = fmaf(__ldg(emb + t * EMB + e), __ldg(W_ih + lane * EMB + e), acc);
    }
    g_proj[t * HID + lane] = acc;
}

__device__ __forceinline__ ull pack2(float lo, float hi) {
    ull u;
    asm("mov.b64 %0, {%1, %2};" : "=l"(u) : "f"(lo), "f"(hi));
    return u;
}
__device__ __forceinline__ ull fma2(ull a, ull b, ull c) {
    asm("fma.rn.f32x2 %0, %1, %2, %3;" : "=l"(c) : "l"(a), "l"(b), "l"(c));
    return c;
}
// 128-bit shared load -> two packed f32x2 operands (volatile: addresses repeat).
__device__ __forceinline__ void lds2(ull& a, ull& b, unsigned addr) {
    asm volatile("ld.shared.v2.u64 {%0, %1}, [%2];" : "=l"(a), "=l"(b) : "r"(addr));
}

// Split-4 layout: lane = (q = lane>>2, c = lane&3).
//  - owns h-chunk k in [8c, 8c+8)  (2 LDS.128/step)
//  - accumulator i = partial for output row  q + 8*(c^i)   (permuted)
//  - FLAT reduce (3 independent shfls, one latency stage)
//  - HW tanh.approx.f32 (single MUFU)
//  - SINGLE h buffer, no syncwarp: hbuf is warp-private; warp never diverges;
//    per-warp in-order LSU orders LDS(s) -> STS(s) -> LDS(s+1).
//  - DISTANCE-4 proj prefetch: covers the ~450cy NAT L2 latency (dist-2 didn't).
__global__ void __launch_bounds__(64, 14) rnn_step_kernel(
    const int* __restrict__ x,
    const float* __restrict__ W_hh,
    const float* __restrict__ W_fc,
    const float* __restrict__ b_fc,
    float* __restrict__ out) {

    int wl   = threadIdx.x >> 5;
    int lane = threadIdx.x & 31;
    int q    = lane >> 2;
    int c    = lane & 3;
    int p    = q + 8 * c;            // the output index this lane finalizes
    int b    = blockIdx.x * 2 + wl;

    __shared__ __align__(16) float hbuf[2][HID];

    // w2[i*4 + t] pairs with accumulator i: W_hh[q + 8*(c^i)][8c + 2t .. +2).
    ull w2[16];
#pragma unroll
    for (int i = 0; i < 4; i++) {
        const float2* wr = (const float2*)(W_hh + (q + 8 * (c ^ i)) * HID + 8 * c);
#pragma unroll
        for (int t = 0; t < 4; t++) {
            float2 wf = __ldg(wr + t);
            w2[i * 4 + t] = pack2(wf.x, wf.y);
        }
    }

    unsigned base = (unsigned)__cvta_generic_to_shared(&hbuf[wl][0]);
    unsigned hb   = base + c * 32;        // load address (own k-chunk)
    unsigned st   = base + p * 4;         // store address for h[p]

    const int4* xb4 = (const int4*)(x + b * SEQ);

    hbuf[wl][lane] = 0.0f;
    __syncwarp();                          // one-time: init visible before loop
    float h = 0.0f;

    // Prime the DISTANCE-4 proj prefetch pipeline (tokens 0..3).
    {
        int4 t0 = __ldg(xb4);
        float xpA = __ldg(&g_proj[t0.x * HID + p]);
        float xpB = __ldg(&g_proj[t0.y * HID + p]);
        float xpC = __ldg(&g_proj[t0.z * HID + p]);
        float xpD = __ldg(&g_proj[t0.w * HID + p]);

#define STEP(XP, TOKPF)                                                        \
    {                                                                          \
        float xu = (XP);                                                       \
        (XP) = __ldg(&g_proj[(TOKPF) * HID + p]); /* refill for s+4 */         \
        ull hp0, hp1, hp2, hp3;                                                \
        lds2(hp0, hp1, hb);                                                    \
        lds2(hp2, hp3, hb + 16);                                               \
        ull a0 = 0, a1 = 0, a2 = 0, a3 = 0;                                    \
        a0 = fma2(hp0, w2[0],  a0); a1 = fma2(hp0, w2[4],  a1);                \
        a2 = fma2(hp0, w2[8],  a2); a3 = fma2(hp0, w2[12], a3);                \
        a0 = fma2(hp1, w2[1],  a0); a1 = fma2(hp1, w2[5],  a1);                \
        a2 = fma2(hp1, w2[9],  a2); a3 = fma2(hp1, w2[13], a3);                \
        a0 = fma2(hp2, w2[2],  a0); a1 = fma2(hp2, w2[6],  a1);                \
        a2 = fma2(hp2, w2[10], a2); a3 = fma2(hp2, w2[14], a3);                \
        a0 = fma2(hp3, w2[3],  a0); a1 = fma2(hp3, w2[7],  a1);                \
        a2 = fma2(hp3, w2[11], a2); a3 = fma2(hp3, w2[15], a3);                \
        float l0, h0, l1, h1, l2, h2, l3, h3;                                  \
        asm("mov.b64 {%0, %1}, %2;" : "=f"(l0), "=f"(h0) : "l"(a0));           \
        asm("mov.b64 {%0, %1}, %2;" : "=f"(l1), "=f"(h1) : "l"(a1));           \
        asm("mov.b64 {%0, %1}, %2;" : "=f"(l2), "=f"(h2) : "l"(a2));           \
        asm("mov.b64 {%0, %1}, %2;" : "=f"(l3), "=f"(h3) : "l"(a3));           \
        float s1 = l1 + h1, s2 = l2 + h2, s3 = l3 + h3;                        \
        float s0 = (l0 + h0) + xu;  /* xu folded in during shfl flight */      \
        float t1 = __shfl_xor_sync(0xffffffffu, s1, 1);                        \
        float t2 = __shfl_xor_sync(0xffffffffu, s2, 2);                        \
        float t3 = __shfl_xor_sync(0xffffffffu, s3, 3);                        \
        float v  = (s0 + t1) + (t2 + t3);                                      \
        asm("tanh.approx.f32 %0, %1;" : "=f"(h) : "f"(v));                     \
        asm volatile("st.shared.f32 [%0], %1;" :: "r"(st), "f"(h) : "memory"); \
    }

        for (int g = 0; g < SEQ / 4 - 1; g++) {
            int4 tn = __ldg(&xb4[g + 1]);         // next group's tokens (s+4..s+7)
            STEP(xpA, tn.x);   // s = 4g+0, refill s+4
            STEP(xpB, tn.y);   // s = 4g+1, refill s+5
            STEP(xpC, tn.z);   // s = 4g+2, refill s+6
            STEP(xpD, tn.w);   // s = 4g+3, refill s+7
        }
        // Final group (g = 127): refills are dead; reuse token 0 (discarded).
        STEP(xpA, t0.x);
        STEP(xpB, t0.x);
        STEP(xpC, t0.x);
        STEP(xpD, t0.x);
#undef STEP
    }

    // Classifier head: lane holds h_final[p]; two full-warp reductions.
    float v0 = h * __ldg(W_fc + p);
    float v1 = h * __ldg(W_fc + HID + p);
#pragma unroll
    for (int o = 16; o > 0; o >>= 1) {
        v0 += __shfl_xor_sync(0xffffffffu, v0, o);
        v1 += __shfl_xor_sync(0xffffffffu, v1, o);
    }
    if (lane == 0) {
        out[b * NCLS + 0] = v0 + __ldg(b_fc + 0);
        out[b * NCLS + 1] = v1 + __ldg(b_fc + 1);
    }
}

extern "C" void kernel_launch(void* const* d_in, const int* in_sizes, int n_in,
                              void* d_out, int out_size) {
    const int*   x    = (const int*)d_in[0];
    const float* emb  = (const float*)d_in[1];
    const float* W_ih = (const float*)d_in[2];
    const float* W_hh = (const float*)d_in[3];
    const float* b_ih = (const float*)d_in[4];
    const float* b_hh = (const float*)d_in[5];
    const float* W_fc = (const float*)d_in[6];
    const float* b_fc = (const float*)d_in[7];
    float* out = (float*)d_out;

    build_proj_kernel<<<(VOCAB + 7) / 8, 256>>>(emb, W_ih, b_ih, b_hh);
    rnn_step_kernel<<<BATCH / 2, 64>>>(x, W_hh, W_fc, b_fc, out);
}

// round 17
// speedup vs baseline: 1.0017x; 1.0017x over previous
#include <cuda_runtime.h>

#define VOCAB 10000
#define EMB   16
#define HID   32
#define NCLS  2
#define BATCH 4096
#define SEQ   512

typedef unsigned long long ull;

// Projected embedding table: proj[t][h] = sum_e emb[t][e]*W_ih[h][e] + b_ih[h] + b_hh[h]
__device__ float g_proj[VOCAB * HID];

__global__ void build_proj_kernel(const float* __restrict__ emb,
                                  const float* __restrict__ W_ih,
                                  const float* __restrict__ b_ih,
                                  const float* __restrict__ b_hh) {
    int t    = blockIdx.x * (blockDim.x >> 5) + (threadIdx.x >> 5);
    int lane = threadIdx.x & 31;
    if (t >= VOCAB) return;
    float acc = __ldg(b_ih + lane) + __ldg(b_hh + lane);
#pragma unroll
    for (int e = 0; e < EMB; e++) {
        acc = fmaf(__ldg(emb + t * EMB + e), __ldg(W_ih + lane * EMB + e), acc);
    }
    g_proj[t * HID + lane] = acc;
}

__device__ __forceinline__ ull pack2(float lo, float hi) {
    ull u;
    asm("mov.b64 %0, {%1, %2};" : "=l"(u) : "f"(lo), "f"(hi));
    return u;
}
__device__ __forceinline__ ull fma2(ull a, ull b, ull c) {
    asm("fma.rn.f32x2 %0, %1, %2, %3;" : "=l"(c) : "l"(a), "l"(b), "l"(c));
    return c;
}
// 128-bit shared load -> two packed f32x2 operands (volatile: addresses repeat).
__device__ __forceinline__ void lds2(ull& a, ull& b, unsigned addr) {
    asm volatile("ld.shared.v2.u64 {%0, %1}, [%2];" : "=l"(a), "=l"(b) : "r"(addr));
}

// ONE WARP PER CTA (4096 single-warp blocks): finest-grain placement so the
// block scheduler can keep all 28 warp-slots/SM filled (2-warp CTAs left
// ~30% of slots empty per ncu).
// Split-4 layout: lane = (q = lane>>2, c = lane&3).
//  - owns h-chunk k in [8c, 8c+8)  (2 LDS.128/step)
//  - accumulator i = partial for output row  q + 8*(c^i)   (permuted)
//  - FLAT reduce (3 independent shfls, one latency stage)
//  - HW tanh.approx.f32 (single MUFU)
//  - single h buffer, no syncwarp (warp-private smem, branch-free loop,
//    in-order per-warp LSU orders STS(s) before LDS(s+1))
//  - distance-4 proj prefetch
__global__ void __launch_bounds__(32, 28) rnn_step_kernel(
    const int* __restrict__ x,
    const float* __restrict__ W_hh,
    const float* __restrict__ W_fc,
    const float* __restrict__ b_fc,
    float* __restrict__ out) {

    int lane = threadIdx.x;
    int q    = lane >> 2;
    int c    = lane & 3;
    int p    = q + 8 * c;            // the output index this lane finalizes
    int b    = blockIdx.x;

    __shared__ __align__(16) float hbuf[HID];

    // w2[i*4 + t] pairs with accumulator i: W_hh[q + 8*(c^i)][8c + 2t .. +2).
    ull w2[16];
#pragma unroll
    for (int i = 0; i < 4; i++) {
        const float2* wr = (const float2*)(W_hh + (q + 8 * (c ^ i)) * HID + 8 * c);
#pragma unroll
        for (int t = 0; t < 4; t++) {
            float2 wf = __ldg(wr + t);
            w2[i * 4 + t] = pack2(wf.x, wf.y);
        }
    }

    unsigned base = (unsigned)__cvta_generic_to_shared(&hbuf[0]);
    unsigned hb   = base + c * 32;        // load address (own k-chunk)
    unsigned st   = base + p * 4;         // store address for h[p]

    const int4* xb4 = (const int4*)(x + b * SEQ);

    hbuf[lane] = 0.0f;
    __syncwarp();                          // one-time: init visible before loop
    float h = 0.0f;

    // Prime the DISTANCE-4 proj prefetch pipeline (tokens 0..3).
    {
        int4 t0 = __ldg(xb4);
        float xpA = __ldg(&g_proj[t0.x * HID + p]);
        float xpB = __ldg(&g_proj[t0.y * HID + p]);
        float xpC = __ldg(&g_proj[t0.z * HID + p]);
        float xpD = __ldg(&g_proj[t0.w * HID + p]);

#define STEP(XP, TOKPF)                                                        \
    {                                                                          \
        float xu = (XP);                                                       \
        (XP) = __ldg(&g_proj[(TOKPF) * HID + p]); /* refill for s+4 */         \
        ull hp0, hp1, hp2, hp3;                                                \
        lds2(hp0, hp1, hb);                                                    \
        lds2(hp2, hp3, hb + 16);                                               \
        ull a0 = 0, a1 = 0, a2 = 0, a3 = 0;                                    \
        a0 = fma2(hp0, w2[0],  a0); a1 = fma2(hp0, w2[4],  a1);                \
        a2 = fma2(hp0, w2[8],  a2); a3 = fma2(hp0, w2[12], a3);                \
        a0 = fma2(hp1, w2[1],  a0); a1 = fma2(hp1, w2[5],  a1);                \
        a2 = fma2(hp1, w2[9],  a2); a3 = fma2(hp1, w2[13], a3);                \
        a0 = fma2(hp2, w2[2],  a0); a1 = fma2(hp2, w2[6],  a1);                \
        a2 = fma2(hp2, w2[10], a2); a3 = fma2(hp2, w2[14], a3);                \
        a0 = fma2(hp3, w2[3],  a0); a1 = fma2(hp3, w2[7],  a1);                \
        a2 = fma2(hp3, w2[11], a2); a3 = fma2(hp3, w2[15], a3);                \
        float l0, h0, l1, h1, l2, h2, l3, h3;                                  \
        asm("mov.b64 {%0, %1}, %2;" : "=f"(l0), "=f"(h0) : "l"(a0));           \
        asm("mov.b64 {%0, %1}, %2;" : "=f"(l1), "=f"(h1) : "l"(a1));           \
        asm("mov.b64 {%0, %1}, %2;" : "=f"(l2), "=f"(h2) : "l"(a2));           \
        asm("mov.b64 {%0, %1}, %2;" : "=f"(l3), "=f"(h3) : "l"(a3));           \
        float s1 = l1 + h1, s2 = l2 + h2, s3 = l3 + h3;                        \
        float s0 = (l0 + h0) + xu;  /* xu folded in during shfl flight */      \
        float t1 = __shfl_xor_sync(0xffffffffu, s1, 1);                        \
        float t2 = __shfl_xor_sync(0xffffffffu, s2, 2);                        \
        float t3 = __shfl_xor_sync(0xffffffffu, s3, 3);                        \
        float v  = (s0 + t1) + (t2 + t3);                                      \
        asm("tanh.approx.f32 %0, %1;" : "=f"(h) : "f"(v));                     \
        asm volatile("st.shared.f32 [%0], %1;" :: "r"(st), "f"(h) : "memory"); \
    }

        for (int g = 0; g < SEQ / 4 - 1; g++) {
            int4 tn = __ldg(&xb4[g + 1]);         // next group's tokens (s+4..s+7)
            STEP(xpA, tn.x);   // s = 4g+0, refill s+4
            STEP(xpB, tn.y);   // s = 4g+1, refill s+5
            STEP(xpC, tn.z);   // s = 4g+2, refill s+6
            STEP(xpD, tn.w);   // s = 4g+3, refill s+7
        }
        // Final group (g = 127): refills are dead; reuse token 0 (discarded).
        STEP(xpA, t0.x);
        STEP(xpB, t0.x);
        STEP(xpC, t0.x);
        STEP(xpD, t0.x);
#undef STEP
    }

    // Classifier head: lane holds h_final[p]; two full-warp reductions.
    float v0 = h * __ldg(W_fc + p);
    float v1 = h * __ldg(W_fc + HID + p);
#pragma unroll
    for (int o = 16; o > 0; o >>= 1) {
        v0 += __shfl_xor_sync(0xffffffffu, v0, o);
        v1 += __shfl_xor_sync(0xffffffffu, v1, o);
    }
    if (lane == 0) {
        out[b * NCLS + 0] = v0 + __ldg(b_fc + 0);
        out[b * NCLS + 1] = v1 + __ldg(b_fc + 1);
    }
}

extern "C" void kernel_launch(void* const* d_in, const int* in_sizes, int n_in,
                              void* d_out, int out_size) {
    const int*   x    = (const int*)d_in[0];
    const float* emb  = (const float*)d_in[1];
    const float* W_ih = (const float*)d_in[2];
    const float* W_hh = (const float*)d_in[3];
    const float* b_ih = (const float*)d_in[4];
    const float* b_hh = (const float*)d_in[5];
    const float* W_fc = (const float*)d_in[6];
    const float* b_fc = (const float*)d_in[7];
    float* out = (float*)d_out;

    build_proj_kernel<<<(VOCAB + 7) / 8, 256>>>(emb, W_ih, b_ih, b_hh);
    rnn_step_kernel<<<BATCH, 32>>>(x, W_hh, W_fc, b_fc, out);
}